// round 1
// baseline (speedup 1.0000x reference)
#include <cuda_runtime.h>
#include <cstdint>

#define NSTEP 16
#define NB 128
#define NE 512
#define NH 8
#define NIN 256
#define NOUT 128
#define NMEM 32769
#define NLAY 2

// ---- scratch (static device globals: allocation-free) ----
__device__ float g_X  [NSTEP * NB * NE];        // projected inputs  [t][b][e]
__device__ float g_h  [NB * NSTEP * NE];        // hidden state      [b][slot][e]
__device__ float g_qkv[NB * NSTEP * 3 * NE];    // qkv               [b][slot][3e]
__device__ float g_att[NB * NSTEP * NE];        // attention output  [b][slot][e]
__device__ float g_tmp[NB * NSTEP * NE];        // gemm epilogue tmp [b][slot][e]

// ============================================================================
// Tiled SGEMM: C[m,n] = sum_k A[m,k] * W[n,k] + bias[n]
// Row m maps to (b = m/L, i = m%L); A row at (b*slotA + i)*K, C row at
// (b*slotC + i)*N.  BM=BN=64, BK=16, 256 threads, 4x4 microtile.
// ============================================================================
__global__ __launch_bounds__(256) void gemm_bias_k(
    const float* __restrict__ A, const float* __restrict__ W,
    const float* __restrict__ bias, float* __restrict__ C,
    int M, int N, int K, int L, int slotA, int slotC)
{
    __shared__ float As[16][68];
    __shared__ float Ws[16][68];
    const int tid = threadIdx.x;
    const int bm = blockIdx.y << 6;
    const int bn = blockIdx.x << 6;

    const int lr = tid >> 2;           // 0..63 : tile row
    const int lk = (tid & 3) << 2;     // 0,4,8,12 : k sub-offset

    const int am = bm + lr;
    const bool avalid = am < M;
    const float* ap = A;
    if (avalid) {
        int b = am / L; int i = am - b * L;
        ap = A + (size_t)(b * slotA + i) * K + lk;
    }
    const float* wp = W + (size_t)(bn + lr) * K + lk;  // N is always a multiple of 64

    const int tm = (tid >> 4) << 2;    // 0..60
    const int tn = (tid & 15) << 2;    // 0..60

    float acc[4][4] = {};

    for (int k0 = 0; k0 < K; k0 += 16) {
        float4 av = make_float4(0.f, 0.f, 0.f, 0.f);
        if (avalid) av = *reinterpret_cast<const float4*>(ap + k0);
        float4 wv = *reinterpret_cast<const float4*>(wp + k0);
        As[lk + 0][lr] = av.x; As[lk + 1][lr] = av.y;
        As[lk + 2][lr] = av.z; As[lk + 3][lr] = av.w;
        Ws[lk + 0][lr] = wv.x; Ws[lk + 1][lr] = wv.y;
        Ws[lk + 2][lr] = wv.z; Ws[lk + 3][lr] = wv.w;
        __syncthreads();
        #pragma unroll
        for (int k = 0; k < 16; k++) {
            float4 a = *reinterpret_cast<const float4*>(&As[k][tm]);
            float4 w = *reinterpret_cast<const float4*>(&Ws[k][tn]);
            acc[0][0] += a.x * w.x; acc[0][1] += a.x * w.y; acc[0][2] += a.x * w.z; acc[0][3] += a.x * w.w;
            acc[1][0] += a.y * w.x; acc[1][1] += a.y * w.y; acc[1][2] += a.y * w.z; acc[1][3] += a.y * w.w;
            acc[2][0] += a.z * w.x; acc[2][1] += a.z * w.y; acc[2][2] += a.z * w.z; acc[2][3] += a.z * w.w;
            acc[3][0] += a.w * w.x; acc[3][1] += a.w * w.y; acc[3][2] += a.w * w.z; acc[3][3] += a.w * w.w;
        }
        __syncthreads();
    }

    float4 bv = *reinterpret_cast<const float4*>(bias + bn + tn);
    #pragma unroll
    for (int i = 0; i < 4; i++) {
        int m = bm + tm + i;
        if (m < M) {
            int b = m / L; int ii = m - b * L;
            float* cp = C + (size_t)(b * slotC + ii) * N + bn + tn;
            cp[0] = acc[i][0] + bv.x; cp[1] = acc[i][1] + bv.y;
            cp[2] = acc[i][2] + bv.z; cp[3] = acc[i][3] + bv.w;
        }
    }
}

// ---- scatter x_t into slot t of h ----
__global__ void scatter_k(int t)
{
    int idx = blockIdx.x * 256 + threadIdx.x;   // 128*512
    int b = idx >> 9, e = idx & 511;
    g_h[((size_t)b * NSTEP + t) * NE + e] = g_X[((size_t)t * NB + b) * NE + e];
}

// ---- per (batch, head) attention over L<=16 valid positions (no mask) ----
__global__ __launch_bounds__(256) void attn_k(int seqL)
{
    __shared__ float q_s[16][64], k_s[16][64], v_s[16][64];
    __shared__ float p_s[16][17];
    int blk = blockIdx.x; int b = blk >> 3; int hh = blk & 7;
    int tid = threadIdx.x;
    const float* base = g_qkv + (size_t)b * NSTEP * 1536 + hh * 64;
    for (int e = tid; e < 1024; e += 256) {
        int i = e >> 6, d = e & 63;
        if (i < seqL) {
            const float* p = base + (size_t)i * 1536 + d;
            q_s[i][d] = p[0];
            k_s[i][d] = p[512];
            v_s[i][d] = p[1024];
        }
    }
    __syncthreads();
    int si = tid >> 4, sj = tid & 15;
    if (si < seqL && sj < seqL) {
        float s = 0.f;
        #pragma unroll
        for (int d = 0; d < 64; d++) s += q_s[si][d] * k_s[sj][d];
        p_s[si][sj] = s * 0.125f;   // 1/sqrt(64)
    }
    __syncthreads();
    if (tid < seqL) {
        float mx = -1e30f;
        for (int j = 0; j < seqL; j++) mx = fmaxf(mx, p_s[tid][j]);
        float sum = 0.f;
        for (int j = 0; j < seqL; j++) { float e = expf(p_s[tid][j] - mx); p_s[tid][j] = e; sum += e; }
        float inv = 1.f / sum;
        for (int j = 0; j < seqL; j++) p_s[tid][j] *= inv;
    }
    __syncthreads();
    int qi = tid >> 4, d0 = (tid & 15) << 2;
    if (qi < seqL) {
        float o0 = 0, o1 = 0, o2 = 0, o3 = 0;
        for (int j = 0; j < seqL; j++) {
            float p = p_s[qi][j];
            o0 += p * v_s[j][d0];     o1 += p * v_s[j][d0 + 1];
            o2 += p * v_s[j][d0 + 2]; o3 += p * v_s[j][d0 + 3];
        }
        float* op = g_att + ((size_t)b * NSTEP + qi) * NE + hh * 64 + d0;
        op[0] = o0; op[1] = o1; op[2] = o2; op[3] = o3;
    }
}

// ---- h = LN(h + tmp) * scale + bias, rowwise over E=512 ----
__global__ __launch_bounds__(256) void resid_ln_k(
    const float* __restrict__ sc, const float* __restrict__ bi, int seqL)
{
    int r = blockIdx.x;
    int b = r / seqL; int i = r - b * seqL;
    float* hp = g_h + ((size_t)b * NSTEP + i) * NE;
    const float* tp = g_tmp + ((size_t)b * NSTEP + i) * NE;
    int tid = threadIdx.x;
    float y0 = hp[tid] + tp[tid];
    float y1 = hp[tid + 256] + tp[tid + 256];
    float s = y0 + y1, ss = y0 * y0 + y1 * y1;
    __shared__ float shs[8], shq[8];
    __shared__ float mu_sh, inv_sh;
    int lane = tid & 31, w = tid >> 5;
    #pragma unroll
    for (int o = 16; o > 0; o >>= 1) {
        s  += __shfl_down_sync(0xffffffffu, s, o);
        ss += __shfl_down_sync(0xffffffffu, ss, o);
    }
    if (lane == 0) { shs[w] = s; shq[w] = ss; }
    __syncthreads();
    if (tid == 0) {
        float ts = 0, tq = 0;
        #pragma unroll
        for (int k = 0; k < 8; k++) { ts += shs[k]; tq += shq[k]; }
        float mu = ts * (1.f / 512.f);
        float var = tq * (1.f / 512.f) - mu * mu;
        mu_sh = mu; inv_sh = rsqrtf(var + 1e-5f);
    }
    __syncthreads();
    float mu = mu_sh, inv = inv_sh;
    hp[tid]       = (y0 - mu) * inv * sc[tid]       + bi[tid];
    hp[tid + 256] = (y1 - mu) * inv * sc[tid + 256] + bi[tid + 256];
}

// ---- out[t,b,:] = h[b, t] @ Wout^T + b_out ----
__global__ __launch_bounds__(128) void outproj_k(
    const float* __restrict__ Wout, const float* __restrict__ b_out,
    float* __restrict__ out, int t)
{
    int b = blockIdx.x, n = threadIdx.x;
    const float4* hr = reinterpret_cast<const float4*>(g_h + ((size_t)b * NSTEP + t) * NE);
    const float4* wr = reinterpret_cast<const float4*>(Wout + (size_t)n * NE);
    float acc = 0.f;
    #pragma unroll 8
    for (int e = 0; e < 128; e++) {
        float4 a = hr[e], w = wr[e];
        acc += a.x * w.x + a.y * w.y + a.z * w.z + a.w * w.w;
    }
    out[((size_t)t * NB + b) * NOUT + n] = acc + b_out[n];
}

// ---- write new_h: [h_fin | pad passthrough | cur_idx+16] ----
__global__ void assemble_k(const float* __restrict__ hstate, float* __restrict__ outh)
{
    int idx = blockIdx.x * 256 + threadIdx.x;
    if (idx >= NB * NMEM) return;
    int b = idx / NMEM; int j = idx - b * NMEM;
    float v;
    if (j < NSTEP * NE)      v = g_h[(size_t)b * NSTEP * NE + j];   // contiguous first 16 rows
    else if (j < NMEM - 1)   v = hstate[idx];                        // untouched pad region
    else                     v = (float)((int)hstate[idx] + NSTEP);  // cur_idx + 16
    outh[idx] = v;
}

extern "C" void kernel_launch(void* const* d_in, const int* in_sizes, int n_in,
                              void* d_out, int out_size)
{
    const float* seq   = (const float*)d_in[0];
    const float* hst   = (const float*)d_in[1];
    const float* Win   = (const float*)d_in[2];
    const float* b_in  = (const float*)d_in[3];
    const float* Wout  = (const float*)d_in[4];
    const float* b_out = (const float*)d_in[5];
    const float* ipw   = (const float*)d_in[6];
    const float* ipb   = (const float*)d_in[7];
    const float* aow   = (const float*)d_in[8];
    const float* aob   = (const float*)d_in[9];
    const float* l1s   = (const float*)d_in[10];
    const float* l1b   = (const float*)d_in[11];
    const float* l2s   = (const float*)d_in[12];
    const float* l2b   = (const float*)d_in[13];
    const float* ffw   = (const float*)d_in[14];
    const float* ffb   = (const float*)d_in[15];
    float* out = (float*)d_out;

    float *pX, *ph, *pqkv, *patt, *ptmp;
    cudaGetSymbolAddress((void**)&pX,   g_X);
    cudaGetSymbolAddress((void**)&ph,   g_h);
    cudaGetSymbolAddress((void**)&pqkv, g_qkv);
    cudaGetSymbolAddress((void**)&patt, g_att);
    cudaGetSymbolAddress((void**)&ptmp, g_tmp);

    // X = sequences @ Win^T + b_in  (contiguous rows: L = M)
    gemm_bias_k<<<dim3(NE / 64, (NSTEP * NB) / 64), 256>>>(
        seq, Win, b_in, pX, NSTEP * NB, NE, NIN, NSTEP * NB, 0, 0);

    for (int t = 0; t < NSTEP; t++) {
        int Lq = t + 1;
        int M = NB * Lq;
        int mt = (M + 63) / 64;

        scatter_k<<<(NB * NE) / 256, 256>>>(t);

        for (int l = 0; l < NLAY; l++) {
            gemm_bias_k<<<dim3(3 * NE / 64, mt), 256>>>(
                ph, ipw + (size_t)l * 3 * NE * NE, ipb + l * 3 * NE, pqkv,
                M, 3 * NE, NE, Lq, NSTEP, NSTEP);
            attn_k<<<NB * NH, 256>>>(Lq);
            gemm_bias_k<<<dim3(NE / 64, mt), 256>>>(
                patt, aow + (size_t)l * NE * NE, aob + l * NE, ptmp,
                M, NE, NE, Lq, NSTEP, NSTEP);
            resid_ln_k<<<M, 256>>>(l1s + l * NE, l1b + l * NE, Lq);
            gemm_bias_k<<<dim3(NE / 64, mt), 256>>>(
                ph, ffw + (size_t)l * NE * NE, ffb + l * NE, ptmp,
                M, NE, NE, Lq, NSTEP, NSTEP);
            resid_ln_k<<<M, 256>>>(l2s + l * NE, l2b + l * NE, Lq);
        }
        outproj_k<<<NB, 128>>>(Wout, b_out, out, t);
    }

    assemble_k<<<(NB * NMEM + 255) / 256, 256>>>(hst, out + NSTEP * NB * NOUT);
}